// round 1
// baseline (speedup 1.0000x reference)
#include <cuda_runtime.h>
#include <math.h>

#define B_ 4
#define S_ 2048
#define D_ 1024
#define GC_ 64
#define EPS_ 1e-6f

// ---------------- scratch (device globals: allocation-guard safe) ----------------
static __device__ __align__(256) float g_Q [(size_t)B_*S_*D_];
static __device__ __align__(256) float g_K [(size_t)B_*S_*D_];
static __device__ __align__(256) float g_V [(size_t)B_*S_*D_];
static __device__ __align__(256) float g_Cv[(size_t)B_*S_*D_];   // conv+LN, later combined
static __device__ __align__(256) float g_Ao[(size_t)B_*S_*D_];   // attention out
static __device__ __align__(256) float g_Sc[(size_t)B_*S_*S_];   // scores / probs

// ---------------- block reductions ----------------
__device__ __forceinline__ float warpSum(float v) {
    #pragma unroll
    for (int o = 16; o > 0; o >>= 1) v += __shfl_xor_sync(0xffffffffu, v, o);
    return v;
}
__device__ __forceinline__ float warpMax(float v) {
    #pragma unroll
    for (int o = 16; o > 0; o >>= 1) v = fmaxf(v, __shfl_xor_sync(0xffffffffu, v, o));
    return v;
}
__device__ __forceinline__ float blockSum(float v, float* red) {
    int t = threadIdx.x, lane = t & 31, w = t >> 5;
    v = warpSum(v);
    if (lane == 0) red[w] = v;
    __syncthreads();
    if (w == 0) {
        float x = (lane < 8) ? red[lane] : 0.f;
        x = warpSum(x);
        if (lane == 0) red[0] = x;
    }
    __syncthreads();
    float r = red[0];
    __syncthreads();
    return r;
}
__device__ __forceinline__ float blockMax(float v, float* red) {
    int t = threadIdx.x, lane = t & 31, w = t >> 5;
    v = warpMax(v);
    if (lane == 0) red[w] = v;
    __syncthreads();
    if (w == 0) {
        float x = (lane < 8) ? red[lane] : -1e30f;
        x = warpMax(x);
        if (lane == 0) red[0] = x;
    }
    __syncthreads();
    float r = red[0];
    __syncthreads();
    return r;
}

// ---------------- tiled SGEMM: C = alpha*A@op(B) (+bias) (+res) ----------------
// TB==0: B is [K,N] row-major (NN).  TB==1: B is [N,K] row-major (NT, C=A@B^T).
// 128x128 tile, BK=16, 256 threads, 8x8 per thread.
// All M,N multiples of 128 and K multiples of 16 in this problem -> no bounds checks.
template <int TB>
__global__ void __launch_bounds__(256) sgemm_kernel(
    const float* __restrict__ A, const float* __restrict__ B,
    const float* __restrict__ bias, const float* __restrict__ res,
    float* __restrict__ C, int M, int N, int Kd,
    long long sA, long long sB, long long sC, float alpha)
{
    __shared__ float As[16][132];
    __shared__ float Bs[16][132];

    const int t  = threadIdx.x;
    const int tx = t & 15, ty = t >> 4;
    const int m0 = blockIdx.y * 128, n0 = blockIdx.x * 128;

    const float* Ab = A + (long long)blockIdx.z * sA;
    const float* Bb = B + (long long)blockIdx.z * sB;
    float*       Cb = C + (long long)blockIdx.z * sC;
    const float* Rb = res ? res + (long long)blockIdx.z * sC : nullptr;

    float acc[8][8];
    #pragma unroll
    for (int i = 0; i < 8; i++)
        #pragma unroll
        for (int j = 0; j < 8; j++) acc[i][j] = 0.f;

    for (int k0 = 0; k0 < Kd; k0 += 16) {
        // A tile: 128 rows x 16 k, transposed store
        #pragma unroll
        for (int i = 0; i < 2; i++) {
            int idx = t + i * 256;
            int row = idx >> 2;
            int kc  = (idx & 3) << 2;
            float4 v = *(const float4*)&Ab[(long long)(m0 + row) * Kd + k0 + kc];
            As[kc + 0][row] = v.x; As[kc + 1][row] = v.y;
            As[kc + 2][row] = v.z; As[kc + 3][row] = v.w;
        }
        if (TB == 0) {
            #pragma unroll
            for (int i = 0; i < 2; i++) {
                int idx = t + i * 256;
                int kr  = idx >> 5;
                int nc  = (idx & 31) << 2;
                float4 v = *(const float4*)&Bb[(long long)(k0 + kr) * N + n0 + nc];
                *(float4*)&Bs[kr][nc] = v;
            }
        } else {
            #pragma unroll
            for (int i = 0; i < 2; i++) {
                int idx = t + i * 256;
                int row = idx >> 2;
                int kc  = (idx & 3) << 2;
                float4 v = *(const float4*)&Bb[(long long)(n0 + row) * Kd + k0 + kc];
                Bs[kc + 0][row] = v.x; Bs[kc + 1][row] = v.y;
                Bs[kc + 2][row] = v.z; Bs[kc + 3][row] = v.w;
            }
        }
        __syncthreads();

        #pragma unroll
        for (int kk = 0; kk < 16; kk++) {
            float a[8], b[8];
            *(float4*)&a[0] = *(const float4*)&As[kk][ty * 4];
            *(float4*)&a[4] = *(const float4*)&As[kk][64 + ty * 4];
            *(float4*)&b[0] = *(const float4*)&Bs[kk][tx * 4];
            *(float4*)&b[4] = *(const float4*)&Bs[kk][64 + tx * 4];
            #pragma unroll
            for (int i = 0; i < 8; i++)
                #pragma unroll
                for (int j = 0; j < 8; j++)
                    acc[i][j] = fmaf(a[i], b[j], acc[i][j]);
        }
        __syncthreads();
    }

    #pragma unroll
    for (int i = 0; i < 8; i++) {
        int r = m0 + ((i < 4) ? (ty * 4 + i) : (64 + ty * 4 + (i - 4)));
        #pragma unroll
        for (int h = 0; h < 2; h++) {
            int c = n0 + h * 64 + tx * 4;
            float4 v;
            v.x = acc[i][h * 4 + 0] * alpha;
            v.y = acc[i][h * 4 + 1] * alpha;
            v.z = acc[i][h * 4 + 2] * alpha;
            v.w = acc[i][h * 4 + 3] * alpha;
            if (bias) {
                float4 bv = *(const float4*)&bias[c];
                v.x += bv.x; v.y += bv.y; v.z += bv.z; v.w += bv.w;
            }
            if (Rb) {
                float4 rv = *(const float4*)&Rb[(long long)r * N + c];
                v.x += rv.x; v.y += rv.y; v.z += rv.z; v.w += rv.w;
            }
            *(float4*)&Cb[(long long)r * N + c] = v;
        }
    }
}

// ---------------- grouped conv1d (K=3, pad=1) + LayerNorm ----------------
// One block handles 4 consecutive sequence positions of one batch.
// Thread t owns channels 4t..4t+3 (all in the same group since 64%4==0).
__global__ void __launch_bounds__(256) conv_ln_kernel(
    const float* __restrict__ x, const float* __restrict__ cw,
    const float* __restrict__ cb, const float* __restrict__ gamma,
    const float* __restrict__ beta)
{
    __shared__ float xs[6][D_];
    __shared__ float red[32];

    const int t  = threadIdx.x;
    const int s0 = blockIdx.x * 4;
    const int b  = blockIdx.y;
    const float* xb = x + (size_t)b * S_ * D_;

    #pragma unroll
    for (int r = 0; r < 6; r++) {
        int sr = s0 - 1 + r;
        if (sr >= 0 && sr < S_) {
            for (int i = t; i < D_; i += 256) xs[r][i] = xb[(size_t)sr * D_ + i];
        } else {
            for (int i = t; i < D_; i += 256) xs[r][i] = 0.f;
        }
    }
    __syncthreads();

    float acc[4][4];   // [dd][position]
    #pragma unroll
    for (int dd = 0; dd < 4; dd++) {
        const int d  = t * 4 + dd;
        const int gb = (d >> 6) << 6;          // group base channel
        const float* wp = cw + (size_t)d * GC_ * 3;
        float a0 = cb[d], a1 = a0, a2 = a0, a3 = a0;
        #pragma unroll 8
        for (int c = 0; c < GC_; c++) {
            float w0 = wp[c * 3 + 0], w1 = wp[c * 3 + 1], w2 = wp[c * 3 + 2];
            float x0 = xs[0][gb + c], x1 = xs[1][gb + c], x2 = xs[2][gb + c];
            float x3 = xs[3][gb + c], x4 = xs[4][gb + c], x5 = xs[5][gb + c];
            a0 += w0 * x0 + w1 * x1 + w2 * x2;
            a1 += w0 * x1 + w1 * x2 + w2 * x3;
            a2 += w0 * x2 + w1 * x3 + w2 * x4;
            a3 += w0 * x3 + w1 * x4 + w2 * x5;
        }
        acc[dd][0] = a0; acc[dd][1] = a1; acc[dd][2] = a2; acc[dd][3] = a3;
    }

    const float4 gv = *(const float4*)&gamma[t * 4];
    const float4 bv = *(const float4*)&beta[t * 4];
    const float gvl[4] = {gv.x, gv.y, gv.z, gv.w};
    const float bvl[4] = {bv.x, bv.y, bv.z, bv.w};

    for (int p = 0; p < 4; p++) {
        float s = acc[0][p] + acc[1][p] + acc[2][p] + acc[3][p];
        float mean = blockSum(s, red) * (1.f / D_);
        float sq = 0.f;
        #pragma unroll
        for (int dd = 0; dd < 4; dd++) { float dl = acc[dd][p] - mean; sq += dl * dl; }
        float var = blockSum(sq, red) * (1.f / (D_ - 1));
        float inv = 1.f / (sqrtf(var) + EPS_);
        float* out = g_Cv + ((size_t)b * S_ + s0 + p) * D_;
        float4 ov;
        ov.x = gvl[0] * (acc[0][p] - mean) * inv + bvl[0];
        ov.y = gvl[1] * (acc[1][p] - mean) * inv + bvl[1];
        ov.z = gvl[2] * (acc[2][p] - mean) * inv + bvl[2];
        ov.w = gvl[3] * (acc[3][p] - mean) * inv + bvl[3];
        *(float4*)&out[t * 4] = ov;
    }
}

// ---------------- row softmax over scores (row length S_) ----------------
__global__ void __launch_bounds__(256) softmax_kernel()
{
    __shared__ float red[32];
    const int t = threadIdx.x;
    float* row = g_Sc + ((size_t)blockIdx.y * S_ + blockIdx.x) * S_;

    float v[8];
    float m = -1e30f;
    #pragma unroll
    for (int j = 0; j < 8; j++) { v[j] = row[t + j * 256]; m = fmaxf(m, v[j]); }
    m = blockMax(m, red);

    float sum = 0.f;
    #pragma unroll
    for (int j = 0; j < 8; j++) { v[j] = __expf(v[j] - m); sum += v[j]; }
    sum = blockSum(sum, red);
    float inv = 1.f / sum;
    #pragma unroll
    for (int j = 0; j < 8; j++) row[t + j * 256] = v[j] * inv;
}

// ---------------- combined = LN(conv_ln + attn_out) -> overwrite g_Cv ----------------
__global__ void __launch_bounds__(256) add_ln_kernel(
    const float* __restrict__ gamma, const float* __restrict__ beta)
{
    __shared__ float red[32];
    const int t = threadIdx.x;
    const size_t row = ((size_t)blockIdx.y * S_ + blockIdx.x) * D_;

    float v[4];
    float s = 0.f;
    #pragma unroll
    for (int j = 0; j < 4; j++) {
        int i = t + j * 256;
        v[j] = g_Cv[row + i] + g_Ao[row + i];
        s += v[j];
    }
    float mean = blockSum(s, red) * (1.f / D_);
    float sq = 0.f;
    #pragma unroll
    for (int j = 0; j < 4; j++) { float dl = v[j] - mean; sq += dl * dl; }
    float var = blockSum(sq, red) * (1.f / (D_ - 1));
    float inv = 1.f / (sqrtf(var) + EPS_);
    #pragma unroll
    for (int j = 0; j < 4; j++) {
        int i = t + j * 256;
        g_Cv[row + i] = gamma[i] * (v[j] - mean) * inv + beta[i];
    }
}

// ---------------- launch ----------------
extern "C" void kernel_launch(void* const* d_in, const int* in_sizes, int n_in,
                              void* d_out, int out_size)
{
    const float* x     = (const float*)d_in[0];
    const float* Wq    = (const float*)d_in[1];
    const float* bq    = (const float*)d_in[2];
    const float* Wk    = (const float*)d_in[3];
    const float* Wv    = (const float*)d_in[4];
    const float* bv    = (const float*)d_in[5];
    const float* cw    = (const float*)d_in[6];
    const float* cb    = (const float*)d_in[7];
    const float* gamma = (const float*)d_in[8];
    const float* beta  = (const float*)d_in[9];
    const float* Wo    = (const float*)d_in[10];
    const float* bo    = (const float*)d_in[11];
    float* out = (float*)d_out;

    float *pQ, *pK, *pV, *pC, *pA, *pS;
    cudaGetSymbolAddress((void**)&pQ, g_Q);
    cudaGetSymbolAddress((void**)&pK, g_K);
    cudaGetSymbolAddress((void**)&pV, g_V);
    cudaGetSymbolAddress((void**)&pC, g_Cv);
    cudaGetSymbolAddress((void**)&pA, g_Ao);
    cudaGetSymbolAddress((void**)&pS, g_Sc);

    const dim3 blk(256);
    const int M = B_ * S_;
    const long long sSD = (long long)S_ * D_;
    const long long sSS = (long long)S_ * S_;

    // QKV projections: [8192,1024] @ [1024,1024]
    dim3 gqkv(D_ / 128, M / 128, 1);
    sgemm_kernel<0><<<gqkv, blk>>>(x, Wq, bq,      nullptr, pQ, M, D_, D_, 0, 0, 0, 1.f);
    sgemm_kernel<0><<<gqkv, blk>>>(x, Wk, nullptr, nullptr, pK, M, D_, D_, 0, 0, 0, 1.f);
    sgemm_kernel<0><<<gqkv, blk>>>(x, Wv, bv,      nullptr, pV, M, D_, D_, 0, 0, 0, 1.f);

    // grouped conv + LN
    conv_ln_kernel<<<dim3(S_ / 4, B_), blk>>>(x, cw, cb, gamma, beta);

    // scores = Q @ K^T * (1/32), per batch
    sgemm_kernel<1><<<dim3(S_ / 128, S_ / 128, B_), blk>>>(
        pQ, pK, nullptr, nullptr, pS, S_, S_, D_, sSD, sSD, sSS, 0.03125f);

    // softmax rows
    softmax_kernel<<<dim3(S_, B_), blk>>>();

    // attn_out = probs @ V, per batch
    sgemm_kernel<0><<<dim3(D_ / 128, S_ / 128, B_), blk>>>(
        pS, pV, nullptr, nullptr, pA, S_, D_, S_, sSS, sSD, sSD, 1.f);

    // combined = LN(conv_ln + attn_out)  (overwrites g_Cv)
    add_ln_kernel<<<dim3(S_, B_), blk>>>(gamma, beta);

    // out = combined @ Wo + bo + x
    sgemm_kernel<0><<<gqkv, blk>>>(pC, Wo, bo, x, out, M, D_, D_, 0, 0, 0, 1.f);
}

// round 4
// speedup vs baseline: 1.7547x; 1.7547x over previous
#include <cuda_runtime.h>
#include <math.h>
#include <stdint.h>

#define B_ 4
#define S_ 2048
#define D_ 1024
#define GC_ 64
#define EPS_ 1e-6f

// GEMM tiling
#define BM 128
#define BN 128
#define BK 32
#define ST_ 3
#define ASTRIDE 36                       // 32 + 4 pad floats
#define STAGE_F (2 * 128 * ASTRIDE)      // floats per stage (A + B)
#define SMEM_DYN (ST_ * STAGE_F * 4)

// ---------------- scratch (device globals: allocation-guard safe) ----------------
static __device__ __align__(256) float g_Xt[(size_t)B_*S_*D_];   // tf32-rounded x
static __device__ __align__(256) float g_Q [(size_t)B_*S_*D_];
static __device__ __align__(256) float g_K [(size_t)B_*S_*D_];
static __device__ __align__(256) float g_V [(size_t)B_*S_*D_];
static __device__ __align__(256) float g_Vt[(size_t)B_*S_*D_];
static __device__ __align__(256) float g_Cv[(size_t)B_*S_*D_];
static __device__ __align__(256) float g_Ao[(size_t)B_*S_*D_];
static __device__ __align__(256) float g_Sc[(size_t)B_*S_*S_];
static __device__ __align__(256) float g_Wt[(size_t)4*D_*D_];

// ---------------- helpers ----------------
__device__ __forceinline__ uint32_t smem_u32(const void* p) {
    uint32_t a;
    asm("{ .reg .u64 t; cvta.to.shared.u64 t, %1; cvt.u32.u64 %0, t; }" : "=r"(a) : "l"(p));
    return a;
}
__device__ __forceinline__ float to_tf32(float x) {
    uint32_t o;
    asm("cvt.rna.tf32.f32 %0, %1;" : "=r"(o) : "f"(x));
    return __uint_as_float(o);
}
__device__ __forceinline__ void cpa16(uint32_t s, const float* g) {
    asm volatile("cp.async.cg.shared.global [%0], [%1], 16;" :: "r"(s), "l"(g));
}
#define CP_COMMIT() asm volatile("cp.async.commit_group;" ::: "memory")
#define CP_WAIT1()  asm volatile("cp.async.wait_group 1;"  ::: "memory")

__device__ __forceinline__ void mma_tf32(float* c, const uint32_t* a, const uint32_t* b) {
    asm volatile(
        "mma.sync.aligned.m16n8k8.row.col.f32.tf32.tf32.f32 "
        "{%0,%1,%2,%3}, {%4,%5,%6,%7}, {%8,%9}, {%0,%1,%2,%3};"
        : "+f"(c[0]), "+f"(c[1]), "+f"(c[2]), "+f"(c[3])
        : "r"(a[0]), "r"(a[1]), "r"(a[2]), "r"(a[3]), "r"(b[0]), "r"(b[1]));
}

// ---------------- mma.sync tf32 GEMM: C = alpha*A@B^T (+bias) (+res) ----------------
// A [M,K] row-major, B [N,K] row-major (both pre-rounded to tf32).
// 128x128x32 tile, 256 threads, 8 warps (4m x 2n), warp tile 32x64.
template <int CVT>
__global__ void __launch_bounds__(256) mma_gemm(
    const float* __restrict__ A, const float* __restrict__ B,
    const float* __restrict__ bias, const float* __restrict__ res,
    float* __restrict__ C, int M, int N, int Kd,
    long long sA, long long sB, long long sC, float alpha)
{
    extern __shared__ __align__(128) float smemf[];
    const uint32_t smem_base = smem_u32(smemf);

    const int t    = threadIdx.x;
    const int wid  = t >> 5;
    const int lane = t & 31;
    const int g    = lane >> 2;       // group row 0..7
    const int q    = lane & 3;        // quad 0..3
    const int wm   = wid & 3;         // warp m 0..3
    const int wn   = wid >> 2;        // warp n 0..1
    const int m0 = blockIdx.y * BM, n0 = blockIdx.x * BN;

    const float* Ab = A + (long long)blockIdx.z * sA;
    const float* Bb = B + (long long)blockIdx.z * sB;
    float*       Cb = C + (long long)blockIdx.z * sC;
    const float* Rb = res ? res + (long long)blockIdx.z * sC : nullptr;

    float acc[2][8][4];
    #pragma unroll
    for (int i = 0; i < 2; i++)
        #pragma unroll
        for (int j = 0; j < 8; j++)
            #pragma unroll
            for (int k = 0; k < 4; k++) acc[i][j][k] = 0.f;

    const int nk = Kd / BK;

    auto load_stage = [&](int j, int s) {
        const int k0 = j * BK;
        const uint32_t sb = smem_base + (uint32_t)s * (STAGE_F * 4);
        #pragma unroll
        for (int i = 0; i < 4; i++) {
            int idx = t + i * 256;
            int row = idx >> 3, c4 = idx & 7;
            cpa16(sb + (uint32_t)(row * ASTRIDE + c4 * 4) * 4,
                  Ab + (long long)(m0 + row) * Kd + k0 + c4 * 4);
        }
        #pragma unroll
        for (int i = 0; i < 4; i++) {
            int idx = t + i * 256;
            int row = idx >> 3, c4 = idx & 7;
            cpa16(sb + (uint32_t)(128 * ASTRIDE + row * ASTRIDE + c4 * 4) * 4,
                  Bb + (long long)(n0 + row) * Kd + k0 + c4 * 4);
        }
    };

    load_stage(0, 0); CP_COMMIT();
    if (nk > 1) load_stage(1, 1);
    CP_COMMIT();

    const int arow = wm * 32;
    const int bcol = wn * 64;

    for (int i = 0; i < nk; i++) {
        const int s = i % ST_;
        CP_WAIT1();
        __syncthreads();
        const int j = i + ST_ - 1;
        if (j < nk) load_stage(j, j % ST_);
        CP_COMMIT();

        const uint32_t* As = (const uint32_t*)(smemf + s * STAGE_F);
        const uint32_t* Bs = As + 128 * ASTRIDE;

        #pragma unroll
        for (int ks = 0; ks < 4; ks++) {
            const int kk = ks * 8;
            uint32_t a[2][4], b[8][2];
            #pragma unroll
            for (int mf = 0; mf < 2; mf++) {
                int r0 = arow + mf * 16 + g;
                a[mf][0] = As[r0 * ASTRIDE + kk + q];
                a[mf][1] = As[(r0 + 8) * ASTRIDE + kk + q];
                a[mf][2] = As[r0 * ASTRIDE + kk + q + 4];
                a[mf][3] = As[(r0 + 8) * ASTRIDE + kk + q + 4];
            }
            #pragma unroll
            for (int nf = 0; nf < 8; nf++) {
                int c0r = bcol + nf * 8 + g;
                b[nf][0] = Bs[c0r * ASTRIDE + kk + q];
                b[nf][1] = Bs[c0r * ASTRIDE + kk + q + 4];
            }
            #pragma unroll
            for (int mf = 0; mf < 2; mf++)
                #pragma unroll
                for (int nf = 0; nf < 8; nf++)
                    mma_tf32(acc[mf][nf], a[mf], b[nf]);
        }
        __syncthreads();
    }

    // epilogue: direct register stores (float2)
    #pragma unroll
    for (int mf = 0; mf < 2; mf++) {
        #pragma unroll
        for (int nf = 0; nf < 8; nf++) {
            const int row = m0 + arow + mf * 16 + g;
            const int col = n0 + bcol + nf * 8 + q * 2;
            float bx = 0.f, by = 0.f;
            if (bias) { bx = bias[col]; by = bias[col + 1]; }
            #pragma unroll
            for (int h = 0; h < 2; h++) {
                const int r = row + h * 8;
                float vx = acc[mf][nf][h * 2 + 0] * alpha + bx;
                float vy = acc[mf][nf][h * 2 + 1] * alpha + by;
                if (Rb) {
                    float2 rv = *(const float2*)&Rb[(long long)r * N + col];
                    vx += rv.x; vy += rv.y;
                }
                if (CVT) { vx = to_tf32(vx); vy = to_tf32(vy); }
                float2 v; v.x = vx; v.y = vy;
                *(float2*)&Cb[(long long)r * N + col] = v;
            }
        }
    }
}

// ---------------- convert x -> tf32-rounded copy ----------------
__global__ void __launch_bounds__(256) convert_kernel(const float* __restrict__ in,
                                                     float* __restrict__ out, int n4)
{
    int i = blockIdx.x * 256 + threadIdx.x;
    if (i < n4) {
        float4 v = ((const float4*)in)[i];
        v.x = to_tf32(v.x); v.y = to_tf32(v.y);
        v.z = to_tf32(v.z); v.w = to_tf32(v.w);
        ((float4*)out)[i] = v;
    }
}

// ---------------- transpose [R,C] -> [C,R], tf32-rounded output ----------------
__global__ void __launch_bounds__(256) transpose_kernel(
    const float* __restrict__ in, float* __restrict__ out,
    int R, int C, long long sIn, long long sOut)
{
    __shared__ float tile[32][33];
    in  += (long long)blockIdx.z * sIn;
    out += (long long)blockIdx.z * sOut;
    const int tx = threadIdx.x & 31, ty = threadIdx.x >> 5;
    const int c0 = blockIdx.x * 32, r0 = blockIdx.y * 32;
    #pragma unroll
    for (int j = 0; j < 4; j++)
        tile[ty + j * 8][tx] = in[(long long)(r0 + ty + j * 8) * C + c0 + tx];
    __syncthreads();
    #pragma unroll
    for (int j = 0; j < 4; j++)
        out[(long long)(c0 + ty + j * 8) * R + r0 + tx] = to_tf32(tile[tx][ty + j * 8]);
}

// ---------------- reductions ----------------
__device__ __forceinline__ float warpSum(float v) {
    #pragma unroll
    for (int o = 16; o > 0; o >>= 1) v += __shfl_xor_sync(0xffffffffu, v, o);
    return v;
}
__device__ __forceinline__ float warpMax(float v) {
    #pragma unroll
    for (int o = 16; o > 0; o >>= 1) v = fmaxf(v, __shfl_xor_sync(0xffffffffu, v, o));
    return v;
}
__device__ __forceinline__ float blockSum(float v, float* red) {
    int t = threadIdx.x, lane = t & 31, w = t >> 5;
    v = warpSum(v);
    if (lane == 0) red[w] = v;
    __syncthreads();
    if (w == 0) {
        float x = (lane < 8) ? red[lane] : 0.f;
        x = warpSum(x);
        if (lane == 0) red[0] = x;
    }
    __syncthreads();
    float r = red[0];
    __syncthreads();
    return r;
}
__device__ __forceinline__ float blockMax(float v, float* red) {
    int t = threadIdx.x, lane = t & 31, w = t >> 5;
    v = warpMax(v);
    if (lane == 0) red[w] = v;
    __syncthreads();
    if (w == 0) {
        float x = (lane < 8) ? red[lane] : -1e30f;
        x = warpMax(x);
        if (lane == 0) red[0] = x;
    }
    __syncthreads();
    float r = red[0];
    __syncthreads();
    return r;
}

// ---------------- grouped conv1d (K=3, pad=1) + LayerNorm ----------------
__global__ void __launch_bounds__(256) conv_ln_kernel(
    const float* __restrict__ x, const float* __restrict__ cw,
    const float* __restrict__ cb, const float* __restrict__ gamma,
    const float* __restrict__ beta)
{
    __shared__ float xs[6][D_];
    __shared__ float red[32];

    const int t  = threadIdx.x;
    const int s0 = blockIdx.x * 4;
    const int b  = blockIdx.y;
    const float* xb = x + (size_t)b * S_ * D_;

    #pragma unroll
    for (int r = 0; r < 6; r++) {
        int sr = s0 - 1 + r;
        if (sr >= 0 && sr < S_) {
            for (int i = t; i < D_; i += 256) xs[r][i] = xb[(size_t)sr * D_ + i];
        } else {
            for (int i = t; i < D_; i += 256) xs[r][i] = 0.f;
        }
    }
    __syncthreads();

    float acc[4][4];
    #pragma unroll
    for (int dd = 0; dd < 4; dd++) {
        const int d  = t * 4 + dd;
        const int gb = (d >> 6) << 6;
        const float* wp = cw + (size_t)d * GC_ * 3;
        float a0 = cb[d], a1 = a0, a2 = a0, a3 = a0;
        #pragma unroll 8
        for (int c = 0; c < GC_; c++) {
            float w0 = wp[c * 3 + 0], w1 = wp[c * 3 + 1], w2 = wp[c * 3 + 2];
            float x0 = xs[0][gb + c], x1 = xs[1][gb + c], x2 = xs[2][gb + c];
            float x3 = xs[3][gb + c], x4 = xs[4][gb + c], x5 = xs[5][gb + c];
            a0 += w0 * x0 + w1 * x1 + w2 * x2;
            a1 += w0 * x1 + w1 * x2 + w2 * x3;
            a2 += w0 * x2 + w1 * x3 + w2 * x4;
            a3 += w0 * x3 + w1 * x4 + w2 * x5;
        }
        acc[dd][0] = a0; acc[dd][1] = a1; acc[dd][2] = a2; acc[dd][3] = a3;
    }

    const float4 gv = *(const float4*)&gamma[t * 4];
    const float4 bv = *(const float4*)&beta[t * 4];
    const float gvl[4] = {gv.x, gv.y, gv.z, gv.w};
    const float bvl[4] = {bv.x, bv.y, bv.z, bv.w};

    for (int p = 0; p < 4; p++) {
        float s = acc[0][p] + acc[1][p] + acc[2][p] + acc[3][p];
        float mean = blockSum(s, red) * (1.f / D_);
        float sq = 0.f;
        #pragma unroll
        for (int dd = 0; dd < 4; dd++) { float dl = acc[dd][p] - mean; sq += dl * dl; }
        float var = blockSum(sq, red) * (1.f / (D_ - 1));
        float inv = 1.f / (sqrtf(var) + EPS_);
        float* out = g_Cv + ((size_t)b * S_ + s0 + p) * D_;
        float4 ov;
        ov.x = gvl[0] * (acc[0][p] - mean) * inv + bvl[0];
        ov.y = gvl[1] * (acc[1][p] - mean) * inv + bvl[1];
        ov.z = gvl[2] * (acc[2][p] - mean) * inv + bvl[2];
        ov.w = gvl[3] * (acc[3][p] - mean) * inv + bvl[3];
        *(float4*)&out[t * 4] = ov;
    }
}

// ---------------- row softmax (writes tf32-rounded probs) ----------------
__global__ void __launch_bounds__(256) softmax_kernel()
{
    __shared__ float red[32];
    const int t = threadIdx.x;
    float* row = g_Sc + ((size_t)blockIdx.y * S_ + blockIdx.x) * S_;

    float v[8];
    float m = -1e30f;
    #pragma unroll
    for (int j = 0; j < 8; j++) { v[j] = row[t + j * 256]; m = fmaxf(m, v[j]); }
    m = blockMax(m, red);

    float sum = 0.f;
    #pragma unroll
    for (int j = 0; j < 8; j++) { v[j] = __expf(v[j] - m); sum += v[j]; }
    sum = blockSum(sum, red);
    float inv = 1.f / sum;
    #pragma unroll
    for (int j = 0; j < 8; j++) row[t + j * 256] = to_tf32(v[j] * inv);
}

// ---------------- combined = LN(conv_ln + attn_out) -> g_Cv (tf32-rounded) ------
__global__ void __launch_bounds__(256) add_ln_kernel(
    const float* __restrict__ gamma, const float* __restrict__ beta)
{
    __shared__ float red[32];
    const int t = threadIdx.x;
    const size_t row = ((size_t)blockIdx.y * S_ + blockIdx.x) * D_;

    float v[4];
    float s = 0.f;
    #pragma unroll
    for (int j = 0; j < 4; j++) {
        int i = t + j * 256;
        v[j] = g_Cv[row + i] + g_Ao[row + i];
        s += v[j];
    }
    float mean = blockSum(s, red) * (1.f / D_);
    float sq = 0.f;
    #pragma unroll
    for (int j = 0; j < 4; j++) { float dl = v[j] - mean; sq += dl * dl; }
    float var = blockSum(sq, red) * (1.f / (D_ - 1));
    float inv = 1.f / (sqrtf(var) + EPS_);
    #pragma unroll
    for (int j = 0; j < 4; j++) {
        int i = t + j * 256;
        g_Cv[row + i] = to_tf32(gamma[i] * (v[j] - mean) * inv + beta[i]);
    }
}

// ---------------- launch ----------------
extern "C" void kernel_launch(void* const* d_in, const int* in_sizes, int n_in,
                              void* d_out, int out_size)
{
    const float* x     = (const float*)d_in[0];
    const float* Wq    = (const float*)d_in[1];
    const float* bq    = (const float*)d_in[2];
    const float* Wk    = (const float*)d_in[3];
    const float* Wv    = (const float*)d_in[4];
    const float* bv    = (const float*)d_in[5];
    const float* cw    = (const float*)d_in[6];
    const float* cb    = (const float*)d_in[7];
    const float* gamma = (const float*)d_in[8];
    const float* beta  = (const float*)d_in[9];
    const float* Wo    = (const float*)d_in[10];
    const float* bo    = (const float*)d_in[11];
    float* out = (float*)d_out;

    float *pXt, *pQ, *pK, *pV, *pVt, *pC, *pA, *pS, *pWt;
    cudaGetSymbolAddress((void**)&pXt, g_Xt);
    cudaGetSymbolAddress((void**)&pQ,  g_Q);
    cudaGetSymbolAddress((void**)&pK,  g_K);
    cudaGetSymbolAddress((void**)&pV,  g_V);
    cudaGetSymbolAddress((void**)&pVt, g_Vt);
    cudaGetSymbolAddress((void**)&pC,  g_Cv);
    cudaGetSymbolAddress((void**)&pA,  g_Ao);
    cudaGetSymbolAddress((void**)&pS,  g_Sc);
    cudaGetSymbolAddress((void**)&pWt, g_Wt);

    cudaFuncSetAttribute(mma_gemm<0>, cudaFuncAttributeMaxDynamicSharedMemorySize, SMEM_DYN);
    cudaFuncSetAttribute(mma_gemm<1>, cudaFuncAttributeMaxDynamicSharedMemorySize, SMEM_DYN);

    const int M = B_ * S_;
    const long long sSD = (long long)S_ * D_;
    const long long sSS = (long long)S_ * S_;
    const long long DD  = (long long)D_ * D_;

    // tf32-round x
    const int n4 = (B_ * S_ * D_) / 4;
    convert_kernel<<<n4 / 256, 256>>>(x, pXt, n4);

    // transpose + round weights
    dim3 tb(256), tgW(D_ / 32, D_ / 32, 1);
    transpose_kernel<<<tgW, tb>>>(Wq, pWt + 0 * DD, D_, D_, 0, 0);
    transpose_kernel<<<tgW, tb>>>(Wk, pWt + 1 * DD, D_, D_, 0, 0);
    transpose_kernel<<<tgW, tb>>>(Wv, pWt + 2 * DD, D_, D_, 0, 0);
    transpose_kernel<<<tgW, tb>>>(Wo, pWt + 3 * DD, D_, D_, 0, 0);

    // QKV projections (Q,K rounded on store; V raw -> rounded by transpose)
    dim3 gblk(256);
    dim3 gqkv(D_ / BN, M / BM, 1);
    mma_gemm<1><<<gqkv, gblk, SMEM_DYN>>>(pXt, pWt + 0 * DD, bq,      nullptr, pQ, M, D_, D_, 0, 0, 0, 1.f);
    mma_gemm<1><<<gqkv, gblk, SMEM_DYN>>>(pXt, pWt + 1 * DD, nullptr, nullptr, pK, M, D_, D_, 0, 0, 0, 1.f);
    mma_gemm<0><<<gqkv, gblk, SMEM_DYN>>>(pXt, pWt + 2 * DD, bv,      nullptr, pV, M, D_, D_, 0, 0, 0, 1.f);

    // grouped conv + LN (uses exact x)
    conv_ln_kernel<<<dim3(S_ / 4, B_), dim3(256)>>>(x, cw, cb, gamma, beta);

    // V^T per batch (rounded)
    transpose_kernel<<<dim3(D_ / 32, S_ / 32, B_), tb>>>(pV, pVt, S_, D_, sSD, sSD);

    // scores = Q @ K^T * (1/32)
    mma_gemm<0><<<dim3(S_ / BN, S_ / BM, B_), gblk, SMEM_DYN>>>(
        pQ, pK, nullptr, nullptr, pS, S_, S_, D_, sSD, sSD, sSS, 0.03125f);

    // softmax rows (rounded probs)
    softmax_kernel<<<dim3(S_, B_), dim3(256)>>>();

    // attn_out = P @ Vt^T = P @ V
    mma_gemm<0><<<dim3(D_ / BN, S_ / BM, B_), gblk, SMEM_DYN>>>(
        pS, pVt, nullptr, nullptr, pA, S_, D_, S_, sSS, sSD, sSD, 1.f);

    // combined = LN(conv_ln + attn_out) (rounded)
    add_ln_kernel<<<dim3(S_, B_), dim3(256)>>>(gamma, beta);

    // out = combined @ Wo^T + bo + x (exact residual)
    mma_gemm<0><<<gqkv, gblk, SMEM_DYN>>>(pC, pWt + 3 * DD, bo, x, out, M, D_, D_, 0, 0, 0, 1.f);
}

// round 6
// speedup vs baseline: 1.8519x; 1.0554x over previous
#include <cuda_runtime.h>
#include <math.h>
#include <stdint.h>

#define B_ 4
#define S_ 2048
#define D_ 1024
#define GC_ 64
#define EPS_ 1e-6f

// GEMM tiling
#define BM 128
#define BN 128
#define BK 32
#define ST_ 4
#define ASTRIDE 36                        // 32 + 4 pad floats
#define STAGE_F (2 * 128 * ASTRIDE)       // floats per stage (A + B)
#define STAGE_BYTES (STAGE_F * 4)
#define SMEM_DYN (ST_ * STAGE_BYTES)

#define BSD ((size_t)B_ * S_ * D_)

// ---------------- scratch (device globals: allocation-guard safe) ----------------
static __device__ __align__(256) float g_Xt [BSD];          // tf32-rounded x
static __device__ __align__(256) float g_QKV[3 * BSD];      // Q | K | V
static __device__ __align__(256) float g_Vt [BSD];
static __device__ __align__(256) float g_Cv [BSD];
static __device__ __align__(256) float g_Ao [BSD];
static __device__ __align__(256) float g_Sc [(size_t)B_*S_*S_];
static __device__ __align__(256) float g_Wt [(size_t)4*D_*D_];  // Wq^T|Wk^T|Wv^T|Wo^T
static __device__ __align__(256) float g_bias[3 * D_];

// ---------------- helpers ----------------
__device__ __forceinline__ uint32_t smem_u32(const void* p) {
    uint32_t a;
    asm("{ .reg .u64 t; cvta.to.shared.u64 t, %1; cvt.u32.u64 %0, t; }" : "=r"(a) : "l"(p));
    return a;
}
__device__ __forceinline__ float to_tf32(float x) {
    uint32_t o;
    asm("cvt.rna.tf32.f32 %0, %1;" : "=r"(o) : "f"(x));
    return __uint_as_float(o);
}
__device__ __forceinline__ void cpa16(uint32_t s, const float* g) {
    asm volatile("cp.async.cg.shared.global [%0], [%1], 16;" :: "r"(s), "l"(g));
}
#define CP_COMMIT() asm volatile("cp.async.commit_group;" ::: "memory")
#define CP_WAIT2()  asm volatile("cp.async.wait_group 2;"  ::: "memory")

__device__ __forceinline__ void ldsm4(uint32_t* r, uint32_t a) {
    asm volatile("ldmatrix.sync.aligned.m8n8.x4.shared.b16 {%0,%1,%2,%3}, [%4];"
        : "=r"(r[0]), "=r"(r[1]), "=r"(r[2]), "=r"(r[3]) : "r"(a));
}
__device__ __forceinline__ void mma_tf32(float* c, const uint32_t* a, const uint32_t* b) {
    asm volatile(
        "mma.sync.aligned.m16n8k8.row.col.f32.tf32.tf32.f32 "
        "{%0,%1,%2,%3}, {%4,%5,%6,%7}, {%8,%9}, {%0,%1,%2,%3};"
        : "+f"(c[0]), "+f"(c[1]), "+f"(c[2]), "+f"(c[3])
        : "r"(a[0]), "r"(a[1]), "r"(a[2]), "r"(a[3]), "r"(b[0]), "r"(b[1]));
}

// ---------------- mma.sync tf32 GEMM: C = alpha*A@B^T (+bias) (+res) ----------------
// A [M,K] row-major, B [N,K] row-major (pre-rounded tf32).
// 128x128x32 tile, 256 threads, 8 warps (4m x 2n), warp tile 32x64.
// SPLIT: output columns 1024-segmented into 3 consecutive [M,1024] buffers.
template <int CVT, int SPLIT>
__global__ void __launch_bounds__(256) mma_gemm(
    const float* __restrict__ A, const float* __restrict__ B,
    const float* __restrict__ bias, const float* __restrict__ res,
    float* __restrict__ C, int M, int N, int Kd,
    long long sA, long long sB, long long sC, float alpha)
{
    extern __shared__ __align__(128) float smemf[];
    const uint32_t smem_base = smem_u32(smemf);

    const int t    = threadIdx.x;
    const int wid  = t >> 5;
    const int lane = t & 31;
    const int g    = lane >> 2;
    const int q    = lane & 3;
    const int wm   = wid & 3;
    const int wn   = wid >> 2;
    const int m0 = blockIdx.y * BM, n0 = blockIdx.x * BN;

    const float* Ab = A + (long long)blockIdx.z * sA;
    const float* Bb = B + (long long)blockIdx.z * sB;
    const float* Rb = res ? res + (long long)blockIdx.z * sC : nullptr;

    float acc[2][8][4];
    #pragma unroll
    for (int i = 0; i < 2; i++)
        #pragma unroll
        for (int j = 0; j < 8; j++)
            #pragma unroll
            for (int k = 0; k < 4; k++) acc[i][j][k] = 0.f;

    const int nk = Kd / BK;

    auto load_stage = [&](int j, int s) {
        const int k0 = j * BK;
        const uint32_t sb = smem_base + (uint32_t)s * STAGE_BYTES;
        #pragma unroll
        for (int i = 0; i < 4; i++) {
            int idx = t + i * 256;
            int row = idx >> 3, c4 = idx & 7;
            cpa16(sb + (uint32_t)(row * ASTRIDE + c4 * 4) * 4,
                  Ab + (long long)(m0 + row) * Kd + k0 + c4 * 4);
        }
        #pragma unroll
        for (int i = 0; i < 4; i++) {
            int idx = t + i * 256;
            int row = idx >> 3, c4 = idx & 7;
            cpa16(sb + (uint32_t)(128 * ASTRIDE + row * ASTRIDE + c4 * 4) * 4,
                  Bb + (long long)(n0 + row) * Kd + k0 + c4 * 4);
        }
    };

    load_stage(0, 0); CP_COMMIT();
    load_stage(1, 1); CP_COMMIT();
    load_stage(2, 2); CP_COMMIT();

    const int arow = wm * 32;
    const int bcol = wn * 64;

    // ldmatrix lane address offsets (bytes within stage A / B regions)
    const int i8 = lane & 7, qd = lane >> 3;
    uint32_t offA[2], offB[4];
    #pragma unroll
    for (int mf = 0; mf < 2; mf++) {
        int row = arow + mf * 16 + i8 + (qd & 1) * 8;
        offA[mf] = (uint32_t)(row * ASTRIDE + (qd >> 1) * 4) * 4;
    }
    #pragma unroll
    for (int p = 0; p < 4; p++) {
        int row = bcol + p * 16 + i8 + (qd >> 1) * 8;
        offB[p] = (uint32_t)(row * ASTRIDE + (qd & 1) * 4) * 4;
    }

    for (int it = 0; it < nk; it++) {
        const int s = it & 3;
        CP_WAIT2();
        __syncthreads();
        const int j = it + 3;
        if (j < nk) load_stage(j, j & 3);
        CP_COMMIT();

        const uint32_t sAb = smem_base + (uint32_t)s * STAGE_BYTES;
        const uint32_t sBb = sAb + (uint32_t)(128 * ASTRIDE * 4);

        uint32_t a[2][2][4], b[2][8][2];
        // preload k-step 0
        #pragma unroll
        for (int mf = 0; mf < 2; mf++) ldsm4(a[0][mf], sAb + offA[mf]);
        #pragma unroll
        for (int p = 0; p < 4; p++) ldsm4(&b[0][2 * p][0], sBb + offB[p]);

        #pragma unroll
        for (int ks = 0; ks < 4; ks++) {
            const int cur = ks & 1, nxt = cur ^ 1;
            if (ks < 3) {
                const uint32_t kb = (uint32_t)((ks + 1) * 8 * 4);
                #pragma unroll
                for (int mf = 0; mf < 2; mf++) ldsm4(a[nxt][mf], sAb + offA[mf] + kb);
                #pragma unroll
                for (int p = 0; p < 4; p++) ldsm4(&b[nxt][2 * p][0], sBb + offB[p] + kb);
            }
            #pragma unroll
            for (int mf = 0; mf < 2; mf++)
                #pragma unroll
                for (int nf = 0; nf < 8; nf++)
                    mma_tf32(acc[mf][nf], a[cur][mf], b[cur][nf]);
        }
    }

    // epilogue
    float* Cb;
    int colBase, rowStride;
    if (SPLIT) {
        Cb = C + (long long)(n0 >> 10) * (long long)(B_ * (size_t)S_ * D_);
        colBase = n0 & 1023;
        rowStride = 1024;
    } else {
        Cb = C + (long long)blockIdx.z * sC;
        colBase = n0;
        rowStride = N;
    }

    #pragma unroll
    for (int mf = 0; mf < 2; mf++) {
        #pragma unroll
        for (int nf = 0; nf < 8; nf++) {
            const int row = m0 + arow + mf * 16 + g;
            const int colG = n0 + bcol + nf * 8 + q * 2;     // bias index
            const int col  = colBase + bcol + nf * 8 + q * 2;
            float bx = 0.f, by = 0.f;
            if (bias) { bx = bias[colG]; by = bias[colG + 1]; }
            #pragma unroll
            for (int h = 0; h < 2; h++) {
                const int r = row + h * 8;
                float vx = acc[mf][nf][h * 2 + 0] * alpha + bx;
                float vy = acc[mf][nf][h * 2 + 1] * alpha + by;
                if (Rb) {
                    float2 rv = *(const float2*)&Rb[(long long)r * rowStride + col];
                    vx += rv.x; vy += rv.y;
                }
                if (CVT) { vx = to_tf32(vx); vy = to_tf32(vy); }
                float2 v; v.x = vx; v.y = vy;
                *(float2*)&Cb[(long long)r * rowStride + col] = v;
            }
        }
    }
}

// ---------------- small utility kernels ----------------
__global__ void __launch_bounds__(256) convert_kernel(const float* __restrict__ in,
                                                     float* __restrict__ out, int n4)
{
    int i = blockIdx.x * 256 + threadIdx.x;
    if (i < n4) {
        float4 v = ((const float4*)in)[i];
        v.x = to_tf32(v.x); v.y = to_tf32(v.y);
        v.z = to_tf32(v.z); v.w = to_tf32(v.w);
        ((float4*)out)[i] = v;
    }
}

__global__ void __launch_bounds__(256) pack_bias_kernel(
    const float* __restrict__ bq, const float* __restrict__ bv, float* __restrict__ o)
{
    int i = blockIdx.x * 256 + threadIdx.x;
    if (i < 3 * D_)
        o[i] = (i < D_) ? bq[i] : ((i < 2 * D_) ? 0.f : bv[i - 2 * D_]);
}

__global__ void __launch_bounds__(256) transpose_kernel(
    const float* __restrict__ in, float* __restrict__ out,
    int R, int C, long long sIn, long long sOut)
{
    __shared__ float tile[32][33];
    in  += (long long)blockIdx.z * sIn;
    out += (long long)blockIdx.z * sOut;
    const int tx = threadIdx.x & 31, ty = threadIdx.x >> 5;
    const int c0 = blockIdx.x * 32, r0 = blockIdx.y * 32;
    #pragma unroll
    for (int j = 0; j < 4; j++)
        tile[ty + j * 8][tx] = in[(long long)(r0 + ty + j * 8) * C + c0 + tx];
    __syncthreads();
    #pragma unroll
    for (int j = 0; j < 4; j++)
        out[(long long)(c0 + ty + j * 8) * R + r0 + tx] = to_tf32(tile[tx][ty + j * 8]);
}

// ---------------- reductions ----------------
__device__ __forceinline__ float warpSum(float v) {
    #pragma unroll
    for (int o = 16; o > 0; o >>= 1) v += __shfl_xor_sync(0xffffffffu, v, o);
    return v;
}
__device__ __forceinline__ float warpMax(float v) {
    #pragma unroll
    for (int o = 16; o > 0; o >>= 1) v = fmaxf(v, __shfl_xor_sync(0xffffffffu, v, o));
    return v;
}
__device__ __forceinline__ float blockSum(float v, float* red) {
    int t = threadIdx.x, lane = t & 31, w = t >> 5;
    v = warpSum(v);
    if (lane == 0) red[w] = v;
    __syncthreads();
    if (w == 0) {
        float x = (lane < 8) ? red[lane] : 0.f;
        x = warpSum(x);
        if (lane == 0) red[0] = x;
    }
    __syncthreads();
    float r = red[0];
    __syncthreads();
    return r;
}
__device__ __forceinline__ float blockMax(float v, float* red) {
    int t = threadIdx.x, lane = t & 31, w = t >> 5;
    v = warpMax(v);
    if (lane == 0) red[w] = v;
    __syncthreads();
    if (w == 0) {
        float x = (lane < 8) ? red[lane] : -1e30f;
        x = warpMax(x);
        if (lane == 0) red[0] = x;
    }
    __syncthreads();
    float r = red[0];
    __syncthreads();
    return r;
}

// ---------------- grouped conv1d (K=3, pad=1) + LayerNorm ----------------
__global__ void __launch_bounds__(256) conv_ln_kernel(
    const float* __restrict__ x, const float* __restrict__ cw,
    const float* __restrict__ cb, const float* __restrict__ gamma,
    const float* __restrict__ beta)
{
    __shared__ float xs[6][D_];
    __shared__ float red[32];

    const int t  = threadIdx.x;
    const int s0 = blockIdx.x * 4;
    const int b  = blockIdx.y;
    const float* xb = x + (size_t)b * S_ * D_;

    #pragma unroll
    for (int r = 0; r < 6; r++) {
        int sr = s0 - 1 + r;
        if (sr >= 0 && sr < S_) {
            for (int i = t; i < D_; i += 256) xs[r][i] = xb[(size_t)sr * D_ + i];
        } else {
            for (int i = t; i < D_; i += 256) xs[r][i] = 0.f;
        }
    }
    __syncthreads();

    float acc[4][4];
    #pragma unroll
    for (int dd = 0; dd < 4; dd++) {
        const int d  = t * 4 + dd;
        const int gb = (d >> 6) << 6;
        const float* wp = cw + (size_t)d * GC_ * 3;
        float a0 = cb[d], a1 = a0, a2 = a0, a3 = a0;
        #pragma unroll 8
        for (int c = 0; c < GC_; c++) {
            float w0 = wp[c * 3 + 0], w1 = wp[c * 3 + 1], w2 = wp[c * 3 + 2];
            float x0 = xs[0][gb + c], x1 = xs[1][gb + c], x2 = xs[2][gb + c];
            float x3 = xs[3][gb + c], x4 = xs[4][gb + c], x5 = xs[5][gb + c];
            a0 += w0 * x0 + w1 * x1 + w2 * x2;
            a1 += w0 * x1 + w1 * x2 + w2 * x3;
            a2 += w0 * x2 + w1 * x3 + w2 * x4;
            a3 += w0 * x3 + w1 * x4 + w2 * x5;
        }
        acc[dd][0] = a0; acc[dd][1] = a1; acc[dd][2] = a2; acc[dd][3] = a3;
    }

    const float4 gv = *(const float4*)&gamma[t * 4];
    const float4 bvv = *(const float4*)&beta[t * 4];
    const float gvl[4] = {gv.x, gv.y, gv.z, gv.w};
    const float bvl[4] = {bvv.x, bvv.y, bvv.z, bvv.w};

    for (int p = 0; p < 4; p++) {
        float s = acc[0][p] + acc[1][p] + acc[2][p] + acc[3][p];
        float mean = blockSum(s, red) * (1.f / D_);
        float sq = 0.f;
        #pragma unroll
        for (int dd = 0; dd < 4; dd++) { float dl = acc[dd][p] - mean; sq += dl * dl; }
        float var = blockSum(sq, red) * (1.f / (D_ - 1));
        float inv = 1.f / (sqrtf(var) + EPS_);
        float* out = g_Cv + ((size_t)b * S_ + s0 + p) * D_;
        float4 ov;
        ov.x = gvl[0] * (acc[0][p] - mean) * inv + bvl[0];
        ov.y = gvl[1] * (acc[1][p] - mean) * inv + bvl[1];
        ov.z = gvl[2] * (acc[2][p] - mean) * inv + bvl[2];
        ov.w = gvl[3] * (acc[3][p] - mean) * inv + bvl[3];
        *(float4*)&out[t * 4] = ov;
    }
}

// ---------------- row softmax (writes tf32-rounded probs) ----------------
__global__ void __launch_bounds__(256) softmax_kernel()
{
    __shared__ float red[32];
    const int t = threadIdx.x;
    float* row = g_Sc + ((size_t)blockIdx.y * S_ + blockIdx.x) * S_;

    float v[8];
    float m = -1e30f;
    #pragma unroll
    for (int j = 0; j < 8; j++) { v[j] = row[t + j * 256]; m = fmaxf(m, v[j]); }
    m = blockMax(m, red);

    float sum = 0.f;
    #pragma unroll
    for (int j = 0; j < 8; j++) { v[j] = __expf(v[j] - m); sum += v[j]; }
    sum = blockSum(sum, red);
    float inv = 1.f / sum;
    #pragma unroll
    for (int j = 0; j < 8; j++) row[t + j * 256] = to_tf32(v[j] * inv);
}

// ---------------- combined = LN(conv_ln + attn_out) -> g_Cv (tf32-rounded) ------
__global__ void __launch_bounds__(256) add_ln_kernel(
    const float* __restrict__ gamma, const float* __restrict__ beta)
{
    __shared__ float red[32];
    const int t = threadIdx.x;
    const size_t row = ((size_t)blockIdx.y * S_ + blockIdx.x) * D_;

    float v[4];
    float s = 0.f;
    #pragma unroll
    for (int j = 0; j < 4; j++) {
        int i = t + j * 256;
        v[j] = g_Cv[row + i] + g_Ao[row + i];
        s += v[j];
    }
    float mean = blockSum(s, red) * (1.f / D_);
    float sq = 0.f;
    #pragma unroll
    for (int j = 0; j < 4; j++) { float dl = v[j] - mean; sq += dl * dl; }
    float var = blockSum(sq, red) * (1.f / (D_ - 1));
    float inv = 1.f / (sqrtf(var) + EPS_);
    #pragma unroll
    for (int j = 0; j < 4; j++) {
        int i = t + j * 256;
        g_Cv[row + i] = to_tf32(gamma[i] * (v[j] - mean) * inv + beta[i]);
    }
}

// ---------------- launch ----------------
extern "C" void kernel_launch(void* const* d_in, const int* in_sizes, int n_in,
                              void* d_out, int out_size)
{
    const float* x     = (const float*)d_in[0];
    const float* Wq    = (const float*)d_in[1];
    const float* bq    = (const float*)d_in[2];
    const float* Wk    = (const float*)d_in[3];
    const float* Wv    = (const float*)d_in[4];
    const float* bv    = (const float*)d_in[5];
    const float* cw    = (const float*)d_in[6];
    const float* cb    = (const float*)d_in[7];
    const float* gamma = (const float*)d_in[8];
    const float* beta  = (const float*)d_in[9];
    const float* Wo    = (const float*)d_in[10];
    const float* bo    = (const float*)d_in[11];
    float* out = (float*)d_out;

    float *pXt, *pQKV, *pVt, *pC, *pA, *pS, *pWt, *pBias;
    cudaGetSymbolAddress((void**)&pXt,  g_Xt);
    cudaGetSymbolAddress((void**)&pQKV, g_QKV);
    cudaGetSymbolAddress((void**)&pVt,  g_Vt);
    cudaGetSymbolAddress((void**)&pC,   g_Cv);
    cudaGetSymbolAddress((void**)&pA,   g_Ao);
    cudaGetSymbolAddress((void**)&pS,   g_Sc);
    cudaGetSymbolAddress((void**)&pWt,  g_Wt);
    cudaGetSymbolAddress((void**)&pBias,g_bias);

    cudaFuncSetAttribute(mma_gemm<0,0>, cudaFuncAttributeMaxDynamicSharedMemorySize, SMEM_DYN);
    cudaFuncSetAttribute(mma_gemm<1,0>, cudaFuncAttributeMaxDynamicSharedMemorySize, SMEM_DYN);
    cudaFuncSetAttribute(mma_gemm<1,1>, cudaFuncAttributeMaxDynamicSharedMemorySize, SMEM_DYN);

    const int M = B_ * S_;
    const long long sSD = (long long)S_ * D_;
    const long long sSS = (long long)S_ * S_;
    const long long DD  = (long long)D_ * D_;

    float* pQ = pQKV;
    float* pK = pQKV + BSD;
    float* pV = pQKV + 2 * BSD;

    // tf32-round x; pack bias
    const int n4 = (B_ * S_ * D_) / 4;
    convert_kernel<<<n4 / 256, 256>>>(x, pXt, n4);
    pack_bias_kernel<<<12, 256>>>(bq, bv, pBias);

    // transpose + round weights
    dim3 tb(256), tgW(D_ / 32, D_ / 32, 1);
    transpose_kernel<<<tgW, tb>>>(Wq, pWt + 0 * DD, D_, D_, 0, 0);
    transpose_kernel<<<tgW, tb>>>(Wk, pWt + 1 * DD, D_, D_, 0, 0);
    transpose_kernel<<<tgW, tb>>>(Wv, pWt + 2 * DD, D_, D_, 0, 0);
    transpose_kernel<<<tgW, tb>>>(Wo, pWt + 3 * DD, D_, D_, 0, 0);

    // fused QKV projection: [8192,1024] @ [3072,1024]^T -> Q|K|V (all tf32-rounded)
    dim3 gblk(256);
    mma_gemm<1,1><<<dim3(3 * D_ / BN, M / BM, 1), gblk, SMEM_DYN>>>(
        pXt, pWt, pBias, nullptr, pQKV, M, 3 * D_, D_, 0, 0, 0, 1.f);

    // grouped conv + LN (uses exact x)
    conv_ln_kernel<<<dim3(S_ / 4, B_), dim3(256)>>>(x, cw, cb, gamma, beta);

    // V^T per batch (rounded)
    transpose_kernel<<<dim3(D_ / 32, S_ / 32, B_), tb>>>(pV, pVt, S_, D_, sSD, sSD);

    // scores = Q @ K^T * (1/32)
    mma_gemm<0,0><<<dim3(S_ / BN, S_ / BM, B_), gblk, SMEM_DYN>>>(
        pQ, pK, nullptr, nullptr, pS, S_, S_, D_, sSD, sSD, sSS, 0.03125f);

    // softmax rows (rounded probs)
    softmax_kernel<<<dim3(S_, B_), dim3(256)>>>();

    // attn_out = P @ Vt^T = P @ V
    mma_gemm<0,0><<<dim3(D_ / BN, S_ / BM, B_), gblk, SMEM_DYN>>>(
        pS, pVt, nullptr, nullptr, pA, S_, D_, S_, sSS, sSD, sSD, 1.f);

    // combined = LN(conv_ln + attn_out) (rounded)
    add_ln_kernel<<<dim3(S_, B_), dim3(256)>>>(gamma, beta);

    // out = combined @ Wo^T + bo + x (exact residual)
    mma_gemm<0,0><<<dim3(D_ / BN, M / BM, 1), gblk, SMEM_DYN>>>(
        pC, pWt + 3 * DD, bo, x, out, M, D_, D_, 0, 0, 0, 1.f);
}

// round 7
// speedup vs baseline: 1.9532x; 1.0547x over previous
#include <cuda_runtime.h>
#include <math.h>
#include <stdint.h>

#define B_ 4
#define S_ 2048
#define D_ 1024
#define GC_ 64
#define EPS_ 1e-6f

// GEMM tiling
#define BM 128
#define BN 128
#define BK 32
#define ST_ 3
#define ASTRIDE 36                        // 32 + 4 pad floats
#define STAGE_F (2 * 128 * ASTRIDE)       // floats per stage (A + B)
#define STAGE_BYTES (STAGE_F * 4)
#define SMEM_DYN (ST_ * STAGE_BYTES)

#define BSD ((size_t)B_ * S_ * D_)

// ---------------- scratch (device globals: allocation-guard safe) ----------------
static __device__ __align__(256) float g_Xt [BSD];          // tf32-rounded x
static __device__ __align__(256) float g_QKV[3 * BSD];      // Q | K | V
static __device__ __align__(256) float g_Vt [BSD];
static __device__ __align__(256) float g_Cv [BSD];
static __device__ __align__(256) float g_Ao [BSD];
static __device__ __align__(256) float g_Sc [(size_t)B_*S_*S_];
static __device__ __align__(256) float g_Wt [(size_t)4*D_*D_];  // Wq^T|Wk^T|Wv^T|Wo^T
static __device__ __align__(256) float g_bias[3 * D_];

// ---------------- helpers ----------------
__device__ __forceinline__ uint32_t smem_u32(const void* p) {
    uint32_t a;
    asm("{ .reg .u64 t; cvta.to.shared.u64 t, %1; cvt.u32.u64 %0, t; }" : "=r"(a) : "l"(p));
    return a;
}
__device__ __forceinline__ float to_tf32(float x) {
    uint32_t o;
    asm("cvt.rna.tf32.f32 %0, %1;" : "=r"(o) : "f"(x));
    return __uint_as_float(o);
}
__device__ __forceinline__ void cpa16(uint32_t s, const float* g) {
    asm volatile("cp.async.cg.shared.global [%0], [%1], 16;" :: "r"(s), "l"(g));
}
#define CP_COMMIT() asm volatile("cp.async.commit_group;" ::: "memory")
#define CP_WAIT1()  asm volatile("cp.async.wait_group 1;"  ::: "memory")

__device__ __forceinline__ void ldsm4(uint32_t* r, uint32_t a) {
    asm volatile("ldmatrix.sync.aligned.m8n8.x4.shared.b16 {%0,%1,%2,%3}, [%4];"
        : "=r"(r[0]), "=r"(r[1]), "=r"(r[2]), "=r"(r[3]) : "r"(a));
}
__device__ __forceinline__ void mma_tf32(float* c, const uint32_t* a, const uint32_t* b) {
    asm volatile(
        "mma.sync.aligned.m16n8k8.row.col.f32.tf32.tf32.f32 "
        "{%0,%1,%2,%3}, {%4,%5,%6,%7}, {%8,%9}, {%0,%1,%2,%3};"
        : "+f"(c[0]), "+f"(c[1]), "+f"(c[2]), "+f"(c[3])
        : "r"(a[0]), "r"(a[1]), "r"(a[2]), "r"(a[3]), "r"(b[0]), "r"(b[1]));
}

// ---------------- mma.sync tf32 GEMM: C = alpha*A@B^T (+bias) (+res) ----------------
// A [M,K] row-major, B [N,K] row-major (pre-rounded tf32).
// 128x128x32 tile, 256 threads, 8 warps (4m x 2n), warp tile 32x64.
// 3-stage cp.async ring, 2 CTAs/SM for cross-CTA latency hiding.
// SPLIT: output columns 1024-segmented into 3 consecutive [M,1024] buffers.
template <int CVT, int SPLIT>
__global__ void __launch_bounds__(256, 2) mma_gemm(
    const float* __restrict__ A, const float* __restrict__ B,
    const float* __restrict__ bias, const float* __restrict__ res,
    float* __restrict__ C, int M, int N, int Kd,
    long long sA, long long sB, long long sC, float alpha)
{
    extern __shared__ __align__(128) float smemf[];
    const uint32_t smem_base = smem_u32(smemf);

    const int t    = threadIdx.x;
    const int wid  = t >> 5;
    const int lane = t & 31;
    const int g    = lane >> 2;
    const int q    = lane & 3;
    const int wm   = wid & 3;
    const int wn   = wid >> 2;
    const int m0 = blockIdx.y * BM, n0 = blockIdx.x * BN;

    const float* Ab = A + (long long)blockIdx.z * sA;
    const float* Bb = B + (long long)blockIdx.z * sB;
    const float* Rb = res ? res + (long long)blockIdx.z * sC : nullptr;

    float acc[2][8][4];
    #pragma unroll
    for (int i = 0; i < 2; i++)
        #pragma unroll
        for (int j = 0; j < 8; j++)
            #pragma unroll
            for (int k = 0; k < 4; k++) acc[i][j][k] = 0.f;

    const int nk = Kd / BK;

    auto load_stage = [&](int j, int s) {
        const int k0 = j * BK;
        const uint32_t sb = smem_base + (uint32_t)s * STAGE_BYTES;
        #pragma unroll
        for (int i = 0; i < 4; i++) {
            int idx = t + i * 256;
            int row = idx >> 3, c4 = idx & 7;
            cpa16(sb + (uint32_t)(row * ASTRIDE + c4 * 4) * 4,
                  Ab + (long long)(m0 + row) * Kd + k0 + c4 * 4);
        }
        #pragma unroll
        for (int i = 0; i < 4; i++) {
            int idx = t + i * 256;
            int row = idx >> 3, c4 = idx & 7;
            cpa16(sb + (uint32_t)(128 * ASTRIDE + row * ASTRIDE + c4 * 4) * 4,
                  Bb + (long long)(n0 + row) * Kd + k0 + c4 * 4);
        }
    };

    load_stage(0, 0); CP_COMMIT();
    load_stage(1, 1); CP_COMMIT();

    const int arow = wm * 32;
    const int bcol = wn * 64;

    // ldmatrix lane address offsets (bytes within stage A / B regions)
    const int i8 = lane & 7, qd = lane >> 3;
    uint32_t offA[2], offB[4];
    #pragma unroll
    for (int mf = 0; mf < 2; mf++) {
        int row = arow + mf * 16 + i8 + (qd & 1) * 8;
        offA[mf] = (uint32_t)(row * ASTRIDE + (qd >> 1) * 4) * 4;
    }
    #pragma unroll
    for (int p = 0; p < 4; p++) {
        int row = bcol + p * 16 + i8 + (qd >> 1) * 8;
        offB[p] = (uint32_t)(row * ASTRIDE + (qd & 1) * 4) * 4;
    }

    int s = 0;
    for (int it = 0; it < nk; it++) {
        CP_WAIT1();
        __syncthreads();
        const int j = it + 2;
        if (j < nk) {
            int sn = s + 2; if (sn >= ST_) sn -= ST_;
            load_stage(j, sn);
        }
        CP_COMMIT();

        const uint32_t sAb = smem_base + (uint32_t)s * STAGE_BYTES;
        const uint32_t sBb = sAb + (uint32_t)(128 * ASTRIDE * 4);

        #pragma unroll
        for (int ks = 0; ks < 4; ks++) {
            const uint32_t kb = (uint32_t)(ks * 8 * 4);
            uint32_t a[2][4], b[8][2];
            #pragma unroll
            for (int mf = 0; mf < 2; mf++) ldsm4(a[mf], sAb + offA[mf] + kb);
            #pragma unroll
            for (int p = 0; p < 4; p++) ldsm4(&b[2 * p][0], sBb + offB[p] + kb);
            #pragma unroll
            for (int mf = 0; mf < 2; mf++)
                #pragma unroll
                for (int nf = 0; nf < 8; nf++)
                    mma_tf32(acc[mf][nf], a[mf], b[nf]);
        }
        __syncthreads();
        if (++s == ST_) s = 0;
    }

    // epilogue
    float* Cb;
    int colBase, rowStride;
    if (SPLIT) {
        Cb = C + (long long)(n0 >> 10) * (long long)(B_ * (size_t)S_ * D_);
        colBase = n0 & 1023;
        rowStride = 1024;
    } else {
        Cb = C + (long long)blockIdx.z * sC;
        colBase = n0;
        rowStride = N;
    }

    #pragma unroll
    for (int mf = 0; mf < 2; mf++) {
        #pragma unroll
        for (int nf = 0; nf < 8; nf++) {
            const int row = m0 + arow + mf * 16 + g;
            const int colG = n0 + bcol + nf * 8 + q * 2;     // bias index
            const int col  = colBase + bcol + nf * 8 + q * 2;
            float bx = 0.f, by = 0.f;
            if (bias) { bx = bias[colG]; by = bias[colG + 1]; }
            #pragma unroll
            for (int h = 0; h < 2; h++) {
                const int r = row + h * 8;
                float vx = acc[mf][nf][h * 2 + 0] * alpha + bx;
                float vy = acc[mf][nf][h * 2 + 1] * alpha + by;
                if (Rb) {
                    float2 rv = *(const float2*)&Rb[(long long)r * rowStride + col];
                    vx += rv.x; vy += rv.y;
                }
                if (CVT) { vx = to_tf32(vx); vy = to_tf32(vy); }
                float2 v; v.x = vx; v.y = vy;
                *(float2*)&Cb[(long long)r * rowStride + col] = v;
            }
        }
    }
}

// ---------------- small utility kernels ----------------
__global__ void __launch_bounds__(256) convert_kernel(const float* __restrict__ in,
                                                     float* __restrict__ out, int n4)
{
    int i = blockIdx.x * 256 + threadIdx.x;
    if (i < n4) {
        float4 v = ((const float4*)in)[i];
        v.x = to_tf32(v.x); v.y = to_tf32(v.y);
        v.z = to_tf32(v.z); v.w = to_tf32(v.w);
        ((float4*)out)[i] = v;
    }
}

__global__ void __launch_bounds__(256) pack_bias_kernel(
    const float* __restrict__ bq, const float* __restrict__ bv, float* __restrict__ o)
{
    int i = blockIdx.x * 256 + threadIdx.x;
    if (i < 3 * D_)
        o[i] = (i < D_) ? bq[i] : ((i < 2 * D_) ? 0.f : bv[i - 2 * D_]);
}

__global__ void __launch_bounds__(256) transpose_kernel(
    const float* __restrict__ in, float* __restrict__ out,
    int R, int C, long long sIn, long long sOut)
{
    __shared__ float tile[32][33];
    in  += (long long)blockIdx.z * sIn;
    out += (long long)blockIdx.z * sOut;
    const int tx = threadIdx.x & 31, ty = threadIdx.x >> 5;
    const int c0 = blockIdx.x * 32, r0 = blockIdx.y * 32;
    #pragma unroll
    for (int j = 0; j < 4; j++)
        tile[ty + j * 8][tx] = in[(long long)(r0 + ty + j * 8) * C + c0 + tx];
    __syncthreads();
    #pragma unroll
    for (int j = 0; j < 4; j++)
        out[(long long)(c0 + ty + j * 8) * R + r0 + tx] = to_tf32(tile[tx][ty + j * 8]);
}

// ---------------- reductions ----------------
__device__ __forceinline__ float warpSum(float v) {
    #pragma unroll
    for (int o = 16; o > 0; o >>= 1) v += __shfl_xor_sync(0xffffffffu, v, o);
    return v;
}
__device__ __forceinline__ float warpMax(float v) {
    #pragma unroll
    for (int o = 16; o > 0; o >>= 1) v = fmaxf(v, __shfl_xor_sync(0xffffffffu, v, o));
    return v;
}
__device__ __forceinline__ float blockSum(float v, float* red) {
    int t = threadIdx.x, lane = t & 31, w = t >> 5;
    v = warpSum(v);
    if (lane == 0) red[w] = v;
    __syncthreads();
    if (w == 0) {
        float x = (lane < 8) ? red[lane] : 0.f;
        x = warpSum(x);
        if (lane == 0) red[0] = x;
    }
    __syncthreads();
    float r = red[0];
    __syncthreads();
    return r;
}
__device__ __forceinline__ float blockMax(float v, float* red) {
    int t = threadIdx.x, lane = t & 31, w = t >> 5;
    v = warpMax(v);
    if (lane == 0) red[w] = v;
    __syncthreads();
    if (w == 0) {
        float x = (lane < 8) ? red[lane] : -1e30f;
        x = warpMax(x);
        if (lane == 0) red[0] = x;
    }
    __syncthreads();
    float r = red[0];
    __syncthreads();
    return r;
}

// ---------------- grouped conv1d (K=3, pad=1) + LayerNorm ----------------
__global__ void __launch_bounds__(256) conv_ln_kernel(
    const float* __restrict__ x, const float* __restrict__ cw,
    const float* __restrict__ cb, const float* __restrict__ gamma,
    const float* __restrict__ beta)
{
    __shared__ float xs[6][D_];
    __shared__ float red[32];

    const int t  = threadIdx.x;
    const int s0 = blockIdx.x * 4;
    const int b  = blockIdx.y;
    const float* xb = x + (size_t)b * S_ * D_;

    #pragma unroll
    for (int r = 0; r < 6; r++) {
        int sr = s0 - 1 + r;
        if (sr >= 0 && sr < S_) {
            for (int i = t; i < D_; i += 256) xs[r][i] = xb[(size_t)sr * D_ + i];
        } else {
            for (int i = t; i < D_; i += 256) xs[r][i] = 0.f;
        }
    }
    __syncthreads();

    float acc[4][4];
    #pragma unroll
    for (int dd = 0; dd < 4; dd++) {
        const int d  = t * 4 + dd;
        const int gb = (d >> 6) << 6;
        const float* wp = cw + (size_t)d * GC_ * 3;
        float a0 = cb[d], a1 = a0, a2 = a0, a3 = a0;
        #pragma unroll 8
        for (int c = 0; c < GC_; c++) {
            float w0 = wp[c * 3 + 0], w1 = wp[c * 3 + 1], w2 = wp[c * 3 + 2];
            float x0 = xs[0][gb + c], x1 = xs[1][gb + c], x2 = xs[2][gb + c];
            float x3 = xs[3][gb + c], x4 = xs[4][gb + c], x5 = xs[5][gb + c];
            a0 += w0 * x0 + w1 * x1 + w2 * x2;
            a1 += w0 * x1 + w1 * x2 + w2 * x3;
            a2 += w0 * x2 + w1 * x3 + w2 * x4;
            a3 += w0 * x3 + w1 * x4 + w2 * x5;
        }
        acc[dd][0] = a0; acc[dd][1] = a1; acc[dd][2] = a2; acc[dd][3] = a3;
    }

    const float4 gv = *(const float4*)&gamma[t * 4];
    const float4 bvv = *(const float4*)&beta[t * 4];
    const float gvl[4] = {gv.x, gv.y, gv.z, gv.w};
    const float bvl[4] = {bvv.x, bvv.y, bvv.z, bvv.w};

    for (int p = 0; p < 4; p++) {
        float s = acc[0][p] + acc[1][p] + acc[2][p] + acc[3][p];
        float mean = blockSum(s, red) * (1.f / D_);
        float sq = 0.f;
        #pragma unroll
        for (int dd = 0; dd < 4; dd++) { float dl = acc[dd][p] - mean; sq += dl * dl; }
        float var = blockSum(sq, red) * (1.f / (D_ - 1));
        float inv = 1.f / (sqrtf(var) + EPS_);
        float* out = g_Cv + ((size_t)b * S_ + s0 + p) * D_;
        float4 ov;
        ov.x = gvl[0] * (acc[0][p] - mean) * inv + bvl[0];
        ov.y = gvl[1] * (acc[1][p] - mean) * inv + bvl[1];
        ov.z = gvl[2] * (acc[2][p] - mean) * inv + bvl[2];
        ov.w = gvl[3] * (acc[3][p] - mean) * inv + bvl[3];
        *(float4*)&out[t * 4] = ov;
    }
}

// ---------------- row softmax (writes tf32-rounded probs) ----------------
__global__ void __launch_bounds__(256) softmax_kernel()
{
    __shared__ float red[32];
    const int t = threadIdx.x;
    float* row = g_Sc + ((size_t)blockIdx.y * S_ + blockIdx.x) * S_;

    float v[8];
    float m = -1e30f;
    #pragma unroll
    for (int j = 0; j < 8; j++) { v[j] = row[t + j * 256]; m = fmaxf(m, v[j]); }
    m = blockMax(m, red);

    float sum = 0.f;
    #pragma unroll
    for (int j = 0; j < 8; j++) { v[j] = __expf(v[j] - m); sum += v[j]; }
    sum = blockSum(sum, red);
    float inv = 1.f / sum;
    #pragma unroll
    for (int j = 0; j < 8; j++) row[t + j * 256] = to_tf32(v[j] * inv);
}

// ---------------- combined = LN(conv_ln + attn_out) -> g_Cv (tf32-rounded) ------
__global__ void __launch_bounds__(256) add_ln_kernel(
    const float* __restrict__ gamma, const float* __restrict__ beta)
{
    __shared__ float red[32];
    const int t = threadIdx.x;
    const size_t row = ((size_t)blockIdx.y * S_ + blockIdx.x) * D_;

    float v[4];
    float s = 0.f;
    #pragma unroll
    for (int j = 0; j < 4; j++) {
        int i = t + j * 256;
        v[j] = g_Cv[row + i] + g_Ao[row + i];
        s += v[j];
    }
    float mean = blockSum(s, red) * (1.f / D_);
    float sq = 0.f;
    #pragma unroll
    for (int j = 0; j < 4; j++) { float dl = v[j] - mean; sq += dl * dl; }
    float var = blockSum(sq, red) * (1.f / (D_ - 1));
    float inv = 1.f / (sqrtf(var) + EPS_);
    #pragma unroll
    for (int j = 0; j < 4; j++) {
        int i = t + j * 256;
        g_Cv[row + i] = to_tf32(gamma[i] * (v[j] - mean) * inv + beta[i]);
    }
}

// ---------------- launch ----------------
extern "C" void kernel_launch(void* const* d_in, const int* in_sizes, int n_in,
                              void* d_out, int out_size)
{
    const float* x     = (const float*)d_in[0];
    const float* Wq    = (const float*)d_in[1];
    const float* bq    = (const float*)d_in[2];
    const float* Wk    = (const float*)d_in[3];
    const float* Wv    = (const float*)d_in[4];
    const float* bv    = (const float*)d_in[5];
    const float* cw    = (const float*)d_in[6];
    const float* cb    = (const float*)d_in[7];
    const float* gamma = (const float*)d_in[8];
    const float* beta  = (const float*)d_in[9];
    const float* Wo    = (const float*)d_in[10];
    const float* bo    = (const float*)d_in[11];
    float* out = (float*)d_out;

    float *pXt, *pQKV, *pVt, *pC, *pA, *pS, *pWt, *pBias;
    cudaGetSymbolAddress((void**)&pXt,  g_Xt);
    cudaGetSymbolAddress((void**)&pQKV, g_QKV);
    cudaGetSymbolAddress((void**)&pVt,  g_Vt);
    cudaGetSymbolAddress((void**)&pC,   g_Cv);
    cudaGetSymbolAddress((void**)&pA,   g_Ao);
    cudaGetSymbolAddress((void**)&pS,   g_Sc);
    cudaGetSymbolAddress((void**)&pWt,  g_Wt);
    cudaGetSymbolAddress((void**)&pBias,g_bias);

    cudaFuncSetAttribute(mma_gemm<0,0>, cudaFuncAttributeMaxDynamicSharedMemorySize, SMEM_DYN);
    cudaFuncSetAttribute(mma_gemm<1,0>, cudaFuncAttributeMaxDynamicSharedMemorySize, SMEM_DYN);
    cudaFuncSetAttribute(mma_gemm<1,1>, cudaFuncAttributeMaxDynamicSharedMemorySize, SMEM_DYN);

    const int M = B_ * S_;
    const long long sSD = (long long)S_ * D_;
    const long long sSS = (long long)S_ * S_;
    const long long DD  = (long long)D_ * D_;

    float* pQ = pQKV;
    float* pK = pQKV + BSD;
    float* pV = pQKV + 2 * BSD;

    // tf32-round x; pack bias
    const int n4 = (B_ * S_ * D_) / 4;
    convert_kernel<<<n4 / 256, 256>>>(x, pXt, n4);
    pack_bias_kernel<<<12, 256>>>(bq, bv, pBias);

    // transpose + round weights
    dim3 tb(256), tgW(D_ / 32, D_ / 32, 1);
    transpose_kernel<<<tgW, tb>>>(Wq, pWt + 0 * DD, D_, D_, 0, 0);
    transpose_kernel<<<tgW, tb>>>(Wk, pWt + 1 * DD, D_, D_, 0, 0);
    transpose_kernel<<<tgW, tb>>>(Wv, pWt + 2 * DD, D_, D_, 0, 0);
    transpose_kernel<<<tgW, tb>>>(Wo, pWt + 3 * DD, D_, D_, 0, 0);

    // fused QKV projection: [8192,1024] @ [3072,1024]^T -> Q|K|V (all tf32-rounded)
    dim3 gblk(256);
    mma_gemm<1,1><<<dim3(3 * D_ / BN, M / BM, 1), gblk, SMEM_DYN>>>(
        pXt, pWt, pBias, nullptr, pQKV, M, 3 * D_, D_, 0, 0, 0, 1.f);

    // grouped conv + LN (uses exact x)
    conv_ln_kernel<<<dim3(S_ / 4, B_), dim3(256)>>>(x, cw, cb, gamma, beta);

    // V^T per batch (rounded)
    transpose_kernel<<<dim3(D_ / 32, S_ / 32, B_), tb>>>(pV, pVt, S_, D_, sSD, sSD);

    // scores = Q @ K^T * (1/32)
    mma_gemm<0,0><<<dim3(S_ / BN, S_ / BM, B_), gblk, SMEM_DYN>>>(
        pQ, pK, nullptr, nullptr, pS, S_, S_, D_, sSD, sSD, sSS, 0.03125f);

    // softmax rows (rounded probs)
    softmax_kernel<<<dim3(S_, B_), dim3(256)>>>();

    // attn_out = P @ Vt^T = P @ V
    mma_gemm<0,0><<<dim3(D_ / BN, S_ / BM, B_), gblk, SMEM_DYN>>>(
        pS, pVt, nullptr, nullptr, pA, S_, D_, S_, sSS, sSD, sSD, 1.f);

    // combined = LN(conv_ln + attn_out) (rounded)
    add_ln_kernel<<<dim3(S_, B_), dim3(256)>>>(gamma, beta);

    // out = combined @ Wo^T + bo + x (exact residual)
    mma_gemm<0,0><<<dim3(D_ / BN, M / BM, 1), gblk, SMEM_DYN>>>(
        pC, pWt + 3 * DD, bo, x, out, M, D_, D_, 0, 0, 0, 1.f);
}